// round 16
// baseline (speedup 1.0000x reference)
#include <cuda_runtime.h>
#include <cuda_bf16.h>
#include <cuda_fp16.h>
#include <cstdint>

// GCNConv forward (converged configuration, best measured 81.9 us):
//   out[i] = dis[i] * ( sum_{(r->i) in E} dis[r]*xw[r] + dis[i]*xw[i] ) + b
//   dis = rsqrt(1 + in_degree)
//
// Pipeline: k1 degree (f32 atomics, 16 edges/thread) -> k2 gemm (128-row tile,
// packed f32x2 FMA; writes fp16 message payload g_sxwh AND fp16 accumulator
// g_acch seeded with the self-loop message; stores g_dis = rsqrt(deg+1);
// re-zeroes g_deg for the next graph replay) -> k3 edge scatter (read-only
// __ldg fp16 gather -> red.global.add.noftz.v4.f16x2, 8 edges per 8-lane
// group) -> k4 finalize (reads g_dis, 4 halfs/thread, 1.6M threads).
//
// g_deg is zero-initialized at module load (first call) and re-zeroed by k2
// (every call) -> no cudaMemsetAsync node; deterministic per replay.
//
// Inputs: x[f32 N*64], edge_index[int32 2*E], W[f32 64*64], b[f32 64]. Out f32 N*64.

#define MAXN 100000
#define D 64

__device__ float g_deg[MAXN];                 // zero at load; k2 re-zeroes
__device__ float g_dis[MAXN];                 // rsqrt(deg+1), written by k2
__device__ uint2 g_sxwh[(size_t)MAXN * 16];   // fp16 messages: 64 halfs / node
__device__ uint2 g_acch[(size_t)MAXN * 16];   // fp16 accumulator: 64 halfs / node

// ---------------------------------------------------------------------------
// K1: degree accumulation over edge targets, 16 edges/thread (4x int4 loads)
// ---------------------------------------------------------------------------
__global__ void k1_degree(const int* __restrict__ ei, int e_cnt)
{
    int t = blockIdx.x * blockDim.x + threadIdx.x;
    int base = t * 16;
    if (base >= e_cnt) return;
    const int* col = ei + e_cnt;
    if (base + 15 < e_cnt) {
        const int4* c4p = (const int4*)col + t * 4;
        int4 c0 = c4p[0];
        int4 c1 = c4p[1];
        int4 c2 = c4p[2];
        int4 c3 = c4p[3];
        atomicAdd(&g_deg[c0.x], 1.0f); atomicAdd(&g_deg[c0.y], 1.0f);
        atomicAdd(&g_deg[c0.z], 1.0f); atomicAdd(&g_deg[c0.w], 1.0f);
        atomicAdd(&g_deg[c1.x], 1.0f); atomicAdd(&g_deg[c1.y], 1.0f);
        atomicAdd(&g_deg[c1.z], 1.0f); atomicAdd(&g_deg[c1.w], 1.0f);
        atomicAdd(&g_deg[c2.x], 1.0f); atomicAdd(&g_deg[c2.y], 1.0f);
        atomicAdd(&g_deg[c2.z], 1.0f); atomicAdd(&g_deg[c2.w], 1.0f);
        atomicAdd(&g_deg[c3.x], 1.0f); atomicAdd(&g_deg[c3.y], 1.0f);
        atomicAdd(&g_deg[c3.z], 1.0f); atomicAdd(&g_deg[c3.w], 1.0f);
    } else {
        for (int i = base; i < e_cnt; i++) atomicAdd(&g_deg[col[i]], 1.0f);
    }
}

// ---------------------------------------------------------------------------
// K2: sxw = rsqrt(deg+1) * (x @ W); writes fp16 payload to g_sxwh AND seeds
//     g_acch with the same value (self-loop message); stores g_dis; then
//     (after __syncthreads) re-zeroes this block's g_deg slab for the next
//     replay.  Register tile: 8 rows x 4 cols/thread, 128 rows/256-thread blk.
// ---------------------------------------------------------------------------
#define GEMM_ROWS 128
#define ROWS_PER_THREAD 8

#define FMA2(acc, xx, ww) \
    asm("fma.rn.f32x2 %0, %1, %2, %0;" : "+l"(acc) : "l"(xx), "l"(ww))
#define SPLAT(xx, f) \
    asm("mov.b64 %0, {%1, %1};" : "=l"(xx) : "f"(f))

__global__ __launch_bounds__(256) void k2_gemm(const float* __restrict__ x,
                                               const float* __restrict__ W,
                                               int n)
{
    __shared__ float Ws[D * D];                 // 16 KB
    __shared__ float4 xs4[GEMM_ROWS * (D / 4)]; // 32 KB

    int tid = threadIdx.x;
    int row0 = blockIdx.x * GEMM_ROWS;

    {
        const float4* W4 = (const float4*)W;
        float4* Ws4 = (float4*)Ws;
#pragma unroll
        for (int i = 0; i < 4; i++) Ws4[tid + i * 256] = W4[tid + i * 256];
    }
    {
        const float4* x4 = (const float4*)x;
#pragma unroll
        for (int i = 0; i < 8; i++) {
            int idx = tid + i * 256;            // float4 index within tile
            int gr = row0 + (idx >> 4);
            float4 v = make_float4(0.f, 0.f, 0.f, 0.f);
            if (gr < n) v = x4[(size_t)row0 * 16 + idx];
            xs4[idx] = v;
        }
    }
    __syncthreads();

    int cg = tid & 15;
    int rg = tid >> 4;
    int c4 = cg * 4;
    int rbase = rg * ROWS_PER_THREAD;

    unsigned long long a01[ROWS_PER_THREAD], a23[ROWS_PER_THREAD];
#pragma unroll
    for (int r = 0; r < ROWS_PER_THREAD; r++) { a01[r] = 0; a23[r] = 0; }

#pragma unroll 4
    for (int k4 = 0; k4 < 16; k4++) {
        ulonglong2 w0 = *(const ulonglong2*)(Ws + (k4 * 4 + 0) * D + c4);
        ulonglong2 w1 = *(const ulonglong2*)(Ws + (k4 * 4 + 1) * D + c4);
        ulonglong2 w2 = *(const ulonglong2*)(Ws + (k4 * 4 + 2) * D + c4);
        ulonglong2 w3 = *(const ulonglong2*)(Ws + (k4 * 4 + 3) * D + c4);
#pragma unroll
        for (int r = 0; r < ROWS_PER_THREAD; r++) {
            float4 xv = xs4[(rbase + r) * 16 + k4];
            unsigned long long xx;
            SPLAT(xx, xv.x); FMA2(a01[r], xx, w0.x); FMA2(a23[r], xx, w0.y);
            SPLAT(xx, xv.y); FMA2(a01[r], xx, w1.x); FMA2(a23[r], xx, w1.y);
            SPLAT(xx, xv.z); FMA2(a01[r], xx, w2.x); FMA2(a23[r], xx, w2.y);
            SPLAT(xx, xv.w); FMA2(a01[r], xx, w3.x); FMA2(a23[r], xx, w3.y);
        }
    }

#pragma unroll
    for (int r = 0; r < ROWS_PER_THREAD; r++) {
        int gr = row0 + rbase + r;
        if (gr < n) {
            float s0, s1, s2, s3;
            asm("mov.b64 {%0, %1}, %2;" : "=f"(s0), "=f"(s1) : "l"(a01[r]));
            asm("mov.b64 {%0, %1}, %2;" : "=f"(s2), "=f"(s3) : "l"(a23[r]));
            float dis = rsqrtf(g_deg[gr] + 1.0f);     // +1 = self loop
            if (cg == 0) g_dis[gr] = dis;             // one writer per row
            __half2 h01 = __floats2half2_rn(s0 * dis, s1 * dis);
            __half2 h23 = __floats2half2_rn(s2 * dis, s3 * dis);
            uint2 pk;
            pk.x = *(unsigned*)&h01;
            pk.y = *(unsigned*)&h23;
            size_t fi = (size_t)gr * 16 + cg;
            g_sxwh[fi] = pk;   // scatter payload
            g_acch[fi] = pk;   // accumulator seeded with self-loop message
        }
    }

    // All reads of this block's g_deg slab are done -> re-zero for next replay.
    __syncthreads();
    if (tid < GEMM_ROWS) {
        int gr = row0 + tid;
        if (gr < n) g_deg[gr] = 0.0f;
    }
}

// ---------------------------------------------------------------------------
// K3: edge scatter — acch[col] += fp16 sxwh[row].  8 lanes x 8 edges/thread:
//     two int4 index loads, 8 __ldg uint4 gathers (read-only path),
//     8 red.global.add.noftz.v4.f16x2.
// ---------------------------------------------------------------------------
__device__ __forceinline__ void redh8(uint4* dst, uint4 v)
{
    asm volatile("red.global.add.noftz.v4.f16x2 [%0], {%1, %2, %3, %4};"
                 :: "l"(dst), "r"(v.x), "r"(v.y), "r"(v.z), "r"(v.w)
                 : "memory");
}

__global__ __launch_bounds__(256) void k3_scatter(const int* __restrict__ ei,
                                                  int e_cnt)
{
    const uint4* src = reinterpret_cast<const uint4*>(g_sxwh);  // 8 uint4 / node
    uint4*       acc = reinterpret_cast<uint4*>(g_acch);

    int t = blockIdx.x * blockDim.x + threadIdx.x;
    int p = t >> 3;                 // oct-of-edges index
    int lane = t & 7;               // 8 lanes x 16B = 128B row
    int base = p * 8;
    if (base >= e_cnt) return;

    if (base + 7 < e_cnt) {
        int4 r0 = __ldg((const int4*)ei + p * 2);
        int4 r1 = __ldg((const int4*)ei + p * 2 + 1);
        int4 c0 = __ldg((const int4*)(ei + e_cnt) + p * 2);
        int4 c1 = __ldg((const int4*)(ei + e_cnt) + p * 2 + 1);

        uint4 v0 = __ldg(src + (size_t)r0.x * 8 + lane);
        uint4 v1 = __ldg(src + (size_t)r0.y * 8 + lane);
        uint4 v2 = __ldg(src + (size_t)r0.z * 8 + lane);
        uint4 v3 = __ldg(src + (size_t)r0.w * 8 + lane);
        uint4 v4 = __ldg(src + (size_t)r1.x * 8 + lane);
        uint4 v5 = __ldg(src + (size_t)r1.y * 8 + lane);
        uint4 v6 = __ldg(src + (size_t)r1.z * 8 + lane);
        uint4 v7 = __ldg(src + (size_t)r1.w * 8 + lane);

        redh8(acc + (size_t)c0.x * 8 + lane, v0);
        redh8(acc + (size_t)c0.y * 8 + lane, v1);
        redh8(acc + (size_t)c0.z * 8 + lane, v2);
        redh8(acc + (size_t)c0.w * 8 + lane, v3);
        redh8(acc + (size_t)c1.x * 8 + lane, v4);
        redh8(acc + (size_t)c1.y * 8 + lane, v5);
        redh8(acc + (size_t)c1.z * 8 + lane, v6);
        redh8(acc + (size_t)c1.w * 8 + lane, v7);
    } else {
        for (int e0 = base; e0 < e_cnt; e0++) {
            uint4 v = __ldg(src + (size_t)ei[e0] * 8 + lane);
            redh8(acc + (size_t)ei[e_cnt + e0] * 8 + lane, v);
        }
    }
}

// ---------------------------------------------------------------------------
// K4: finalize — out = g_dis[node] * float(acc) + b.  Finest grain: one uint2
//     (4 halfs) per thread, n*16 threads; two independent loads (dis, acc).
// ---------------------------------------------------------------------------
__global__ void k4_final(float* __restrict__ out, const float* __restrict__ b,
                         int n)
{
    int t = blockIdx.x * blockDim.x + threadIdx.x;
    if (t >= n * 16) return;
    int node = t >> 4;
    int c4 = (t & 15) * 4;          // 4 halfs: cols c4 .. c4+3

    float dis = g_dis[node];
    uint2 h = g_acch[t];
    float2 f01 = __half22float2(*(__half2*)&h.x);
    float2 f23 = __half22float2(*(__half2*)&h.y);
    float4 bb = *(const float4*)(b + c4);

    float4 o;
    o.x = dis * f01.x + bb.x;
    o.y = dis * f01.y + bb.y;
    o.z = dis * f23.x + bb.z;
    o.w = dis * f23.y + bb.w;
    ((float4*)out)[t] = o;
}

// ---------------------------------------------------------------------------
extern "C" void kernel_launch(void* const* d_in, const int* in_sizes, int n_in,
                              void* d_out, int out_size)
{
    const float* x  = (const float*)d_in[0];
    const int*   ei = (const int*)d_in[1];     // int32
    const float* W  = (const float*)d_in[2];
    const float* b  = (const float*)d_in[3];
    float* out = (float*)d_out;

    int n = in_sizes[0] / D;       // 100000
    int e = in_sizes[1] / 2;       // 1600000

    // K1: degree counts (16 edges/thread); g_deg zeroed at load (call 1) and
    // by k2 (every call).
    {
        int threads = 256;
        int groups = (e + 15) / 16;
        k1_degree<<<(groups + threads - 1) / threads, threads>>>(ei, e);
    }
    // K2: gemm -> fp16 payload + seeded fp16 accumulator + g_dis + deg reset
    {
        int blocks = (n + GEMM_ROWS - 1) / GEMM_ROWS;
        k2_gemm<<<blocks, 256>>>(x, W, n);
    }
    // K3: edge scatter-add (8 edges per 8-lane group, read-only gathers)
    {
        long long octs = (e + 7) / 8;
        long long total = octs * 8;
        int threads = 256;
        k3_scatter<<<(unsigned)((total + threads - 1) / threads), threads>>>(ei, e);
    }
    // K4: finalize (4 halfs / thread, 1.6M threads)
    {
        int total = n * 16;
        int threads = 256;
        k4_final<<<(total + threads - 1) / threads, threads>>>(out, b, n);
    }
}

// round 17
// speedup vs baseline: 1.0004x; 1.0004x over previous
#include <cuda_runtime.h>
#include <cuda_bf16.h>
#include <cuda_fp16.h>
#include <cstdint>

// GCNConv forward — FINAL converged kernel (best measured 81.888 us).
//   out[i] = dis[i] * ( sum_{(r->i) in E} dis[r]*xw[r] + dis[i]*xw[i] ) + b
//   dis = rsqrt(1 + in_degree)
//
// Pipeline:
//   k1 degree   — f32 global REDs, 16 edges/thread (spread-address floor)
//   k2 gemm     — 128-row tile, packed f32x2 FMA (FFMA2 issue floor);
//                 emits fp16 message payload g_sxwh, seeds fp16 accumulator
//                 g_acch with the self-loop message, stores g_dis, and
//                 re-zeroes g_deg for the next graph replay
//   k3 scatter  — fp16 gather + red.global.add.noftz.v4.f16x2,
//                 8 edges per 8-lane group (LTS byte floor: ~628 MB)
//   k4 finalize — out = g_dis * float(acc) + b, 4 halfs/thread (DRAM stream)
//
// g_deg is zero-initialized at module load (first call) and re-zeroed by k2
// (every call) -> no memset node; deterministic and graph-replay-safe.
//
// Precision: messages+accumulator in fp16, rel_err ~6.76e-4 (< 1e-3 gate,
// 1.5x margin). Self term and all scaling factors computed in fp32.
//
// Inputs: x[f32 N*64], edge_index[int32 2*E], W[f32 64*64], b[f32 64]. Out f32 N*64.

#define MAXN 100000
#define D 64

__device__ float g_deg[MAXN];                 // zero at load; k2 re-zeroes
__device__ float g_dis[MAXN];                 // rsqrt(deg+1), written by k2
__device__ uint2 g_sxwh[(size_t)MAXN * 16];   // fp16 messages: 64 halfs / node
__device__ uint2 g_acch[(size_t)MAXN * 16];   // fp16 accumulator: 64 halfs / node

// ---------------------------------------------------------------------------
// K1: degree accumulation over edge targets, 16 edges/thread (4x int4 loads)
// ---------------------------------------------------------------------------
__global__ void k1_degree(const int* __restrict__ ei, int e_cnt)
{
    int t = blockIdx.x * blockDim.x + threadIdx.x;
    int base = t * 16;
    if (base >= e_cnt) return;
    const int* col = ei + e_cnt;
    if (base + 15 < e_cnt) {
        const int4* c4p = (const int4*)col + t * 4;
        int4 c0 = c4p[0];
        int4 c1 = c4p[1];
        int4 c2 = c4p[2];
        int4 c3 = c4p[3];
        atomicAdd(&g_deg[c0.x], 1.0f); atomicAdd(&g_deg[c0.y], 1.0f);
        atomicAdd(&g_deg[c0.z], 1.0f); atomicAdd(&g_deg[c0.w], 1.0f);
        atomicAdd(&g_deg[c1.x], 1.0f); atomicAdd(&g_deg[c1.y], 1.0f);
        atomicAdd(&g_deg[c1.z], 1.0f); atomicAdd(&g_deg[c1.w], 1.0f);
        atomicAdd(&g_deg[c2.x], 1.0f); atomicAdd(&g_deg[c2.y], 1.0f);
        atomicAdd(&g_deg[c2.z], 1.0f); atomicAdd(&g_deg[c2.w], 1.0f);
        atomicAdd(&g_deg[c3.x], 1.0f); atomicAdd(&g_deg[c3.y], 1.0f);
        atomicAdd(&g_deg[c3.z], 1.0f); atomicAdd(&g_deg[c3.w], 1.0f);
    } else {
        for (int i = base; i < e_cnt; i++) atomicAdd(&g_deg[col[i]], 1.0f);
    }
}

// ---------------------------------------------------------------------------
// K2: sxw = rsqrt(deg+1) * (x @ W); writes fp16 payload to g_sxwh AND seeds
//     g_acch with the same value (self-loop message); stores g_dis; then
//     (after __syncthreads) re-zeroes this block's g_deg slab for the next
//     replay.  Register tile: 8 rows x 4 cols/thread, 128 rows/256-thread blk.
// ---------------------------------------------------------------------------
#define GEMM_ROWS 128
#define ROWS_PER_THREAD 8

#define FMA2(acc, xx, ww) \
    asm("fma.rn.f32x2 %0, %1, %2, %0;" : "+l"(acc) : "l"(xx), "l"(ww))
#define SPLAT(xx, f) \
    asm("mov.b64 %0, {%1, %1};" : "=l"(xx) : "f"(f))

__global__ __launch_bounds__(256) void k2_gemm(const float* __restrict__ x,
                                               const float* __restrict__ W,
                                               int n)
{
    __shared__ float Ws[D * D];                 // 16 KB
    __shared__ float4 xs4[GEMM_ROWS * (D / 4)]; // 32 KB

    int tid = threadIdx.x;
    int row0 = blockIdx.x * GEMM_ROWS;

    {
        const float4* W4 = (const float4*)W;
        float4* Ws4 = (float4*)Ws;
#pragma unroll
        for (int i = 0; i < 4; i++) Ws4[tid + i * 256] = W4[tid + i * 256];
    }
    {
        const float4* x4 = (const float4*)x;
#pragma unroll
        for (int i = 0; i < 8; i++) {
            int idx = tid + i * 256;            // float4 index within tile
            int gr = row0 + (idx >> 4);
            float4 v = make_float4(0.f, 0.f, 0.f, 0.f);
            if (gr < n) v = x4[(size_t)row0 * 16 + idx];
            xs4[idx] = v;
        }
    }
    __syncthreads();

    int cg = tid & 15;
    int rg = tid >> 4;
    int c4 = cg * 4;
    int rbase = rg * ROWS_PER_THREAD;

    unsigned long long a01[ROWS_PER_THREAD], a23[ROWS_PER_THREAD];
#pragma unroll
    for (int r = 0; r < ROWS_PER_THREAD; r++) { a01[r] = 0; a23[r] = 0; }

#pragma unroll 4
    for (int k4 = 0; k4 < 16; k4++) {
        ulonglong2 w0 = *(const ulonglong2*)(Ws + (k4 * 4 + 0) * D + c4);
        ulonglong2 w1 = *(const ulonglong2*)(Ws + (k4 * 4 + 1) * D + c4);
        ulonglong2 w2 = *(const ulonglong2*)(Ws + (k4 * 4 + 2) * D + c4);
        ulonglong2 w3 = *(const ulonglong2*)(Ws + (k4 * 4 + 3) * D + c4);
#pragma unroll
        for (int r = 0; r < ROWS_PER_THREAD; r++) {
            float4 xv = xs4[(rbase + r) * 16 + k4];
            unsigned long long xx;
            SPLAT(xx, xv.x); FMA2(a01[r], xx, w0.x); FMA2(a23[r], xx, w0.y);
            SPLAT(xx, xv.y); FMA2(a01[r], xx, w1.x); FMA2(a23[r], xx, w1.y);
            SPLAT(xx, xv.z); FMA2(a01[r], xx, w2.x); FMA2(a23[r], xx, w2.y);
            SPLAT(xx, xv.w); FMA2(a01[r], xx, w3.x); FMA2(a23[r], xx, w3.y);
        }
    }

#pragma unroll
    for (int r = 0; r < ROWS_PER_THREAD; r++) {
        int gr = row0 + rbase + r;
        if (gr < n) {
            float s0, s1, s2, s3;
            asm("mov.b64 {%0, %1}, %2;" : "=f"(s0), "=f"(s1) : "l"(a01[r]));
            asm("mov.b64 {%0, %1}, %2;" : "=f"(s2), "=f"(s3) : "l"(a23[r]));
            float dis = rsqrtf(g_deg[gr] + 1.0f);     // +1 = self loop
            if (cg == 0) g_dis[gr] = dis;             // one writer per row
            __half2 h01 = __floats2half2_rn(s0 * dis, s1 * dis);
            __half2 h23 = __floats2half2_rn(s2 * dis, s3 * dis);
            uint2 pk;
            pk.x = *(unsigned*)&h01;
            pk.y = *(unsigned*)&h23;
            size_t fi = (size_t)gr * 16 + cg;
            g_sxwh[fi] = pk;   // scatter payload
            g_acch[fi] = pk;   // accumulator seeded with self-loop message
        }
    }

    // All reads of this block's g_deg slab are done -> re-zero for next replay.
    __syncthreads();
    if (tid < GEMM_ROWS) {
        int gr = row0 + tid;
        if (gr < n) g_deg[gr] = 0.0f;
    }
}

// ---------------------------------------------------------------------------
// K3: edge scatter — acch[col] += fp16 sxwh[row].  8 lanes x 8 edges/thread:
//     two int4 index loads, 8 uint4 gathers, 8 red.global.add.noftz.v4.f16x2.
// ---------------------------------------------------------------------------
__device__ __forceinline__ void redh8(uint4* dst, uint4 v)
{
    asm volatile("red.global.add.noftz.v4.f16x2 [%0], {%1, %2, %3, %4};"
                 :: "l"(dst), "r"(v.x), "r"(v.y), "r"(v.z), "r"(v.w)
                 : "memory");
}

__global__ __launch_bounds__(256) void k3_scatter(const int* __restrict__ ei,
                                                  int e_cnt)
{
    const uint4* src = reinterpret_cast<const uint4*>(g_sxwh);  // 8 uint4 / node
    uint4*       acc = reinterpret_cast<uint4*>(g_acch);

    int t = blockIdx.x * blockDim.x + threadIdx.x;
    int p = t >> 3;                 // oct-of-edges index
    int lane = t & 7;               // 8 lanes x 16B = 128B row
    int base = p * 8;
    if (base >= e_cnt) return;

    if (base + 7 < e_cnt) {
        int4 r0 = ((const int4*)ei)[p * 2];
        int4 r1 = ((const int4*)ei)[p * 2 + 1];
        int4 c0 = ((const int4*)(ei + e_cnt))[p * 2];
        int4 c1 = ((const int4*)(ei + e_cnt))[p * 2 + 1];

        uint4 v0 = src[(size_t)r0.x * 8 + lane];
        uint4 v1 = src[(size_t)r0.y * 8 + lane];
        uint4 v2 = src[(size_t)r0.z * 8 + lane];
        uint4 v3 = src[(size_t)r0.w * 8 + lane];
        uint4 v4 = src[(size_t)r1.x * 8 + lane];
        uint4 v5 = src[(size_t)r1.y * 8 + lane];
        uint4 v6 = src[(size_t)r1.z * 8 + lane];
        uint4 v7 = src[(size_t)r1.w * 8 + lane];

        redh8(acc + (size_t)c0.x * 8 + lane, v0);
        redh8(acc + (size_t)c0.y * 8 + lane, v1);
        redh8(acc + (size_t)c0.z * 8 + lane, v2);
        redh8(acc + (size_t)c0.w * 8 + lane, v3);
        redh8(acc + (size_t)c1.x * 8 + lane, v4);
        redh8(acc + (size_t)c1.y * 8 + lane, v5);
        redh8(acc + (size_t)c1.z * 8 + lane, v6);
        redh8(acc + (size_t)c1.w * 8 + lane, v7);
    } else {
        for (int e0 = base; e0 < e_cnt; e0++) {
            uint4 v = src[(size_t)ei[e0] * 8 + lane];
            redh8(acc + (size_t)ei[e_cnt + e0] * 8 + lane, v);
        }
    }
}

// ---------------------------------------------------------------------------
// K4: finalize — out = g_dis[node] * float(acc) + b.  Finest grain: one uint2
//     (4 halfs) per thread, n*16 threads; two independent loads (dis, acc).
// ---------------------------------------------------------------------------
__global__ void k4_final(float* __restrict__ out, const float* __restrict__ b,
                         int n)
{
    int t = blockIdx.x * blockDim.x + threadIdx.x;
    if (t >= n * 16) return;
    int node = t >> 4;
    int c4 = (t & 15) * 4;          // 4 halfs: cols c4 .. c4+3

    float dis = g_dis[node];
    uint2 h = g_acch[t];
    float2 f01 = __half22float2(*(__half2*)&h.x);
    float2 f23 = __half22float2(*(__half2*)&h.y);
    float4 bb = *(const float4*)(b + c4);

    float4 o;
    o.x = dis * f01.x + bb.x;
    o.y = dis * f01.y + bb.y;
    o.z = dis * f23.x + bb.z;
    o.w = dis * f23.y + bb.w;
    ((float4*)out)[t] = o;
}

// ---------------------------------------------------------------------------
extern "C" void kernel_launch(void* const* d_in, const int* in_sizes, int n_in,
                              void* d_out, int out_size)
{
    const float* x  = (const float*)d_in[0];
    const int*   ei = (const int*)d_in[1];     // int32
    const float* W  = (const float*)d_in[2];
    const float* b  = (const float*)d_in[3];
    float* out = (float*)d_out;

    int n = in_sizes[0] / D;       // 100000
    int e = in_sizes[1] / 2;       // 1600000

    // K1: degree counts (16 edges/thread); g_deg zeroed at load (call 1) and
    // by k2 (every call).
    {
        int threads = 256;
        int groups = (e + 15) / 16;
        k1_degree<<<(groups + threads - 1) / threads, threads>>>(ei, e);
    }
    // K2: gemm -> fp16 payload + seeded fp16 accumulator + g_dis + deg reset
    {
        int blocks = (n + GEMM_ROWS - 1) / GEMM_ROWS;
        k2_gemm<<<blocks, 256>>>(x, W, n);
    }
    // K3: edge scatter-add (8 edges per 8-lane group)
    {
        long long octs = (e + 7) / 8;
        long long total = octs * 8;
        int threads = 256;
        k3_scatter<<<(unsigned)((total + threads - 1) / threads), threads>>>(ei, e);
    }
    // K4: finalize (4 halfs / thread, 1.6M threads)
    {
        int total = n * 16;
        int threads = 256;
        k4_final<<<(total + threads - 1) / threads, threads>>>(out, b, n);
    }
}